// round 7
// baseline (speedup 1.0000x reference)
#include <cuda_runtime.h>
#include <cuda_fp16.h>
#include <cstdint>

#define CIN 18
#define HH  256
#define WW  256
#define OCN 64
#define HWX (HH * WW)
#define NCHUNK 9

#define SMEM_A0 0
#define SMEM_A1 32768
#define SMEM_B  65536
#define SMEM_TOTAL (65536 + NCHUNK * 8192)   // 139264 B

#define SW(o) ((o) ^ (((o) >> 3) & 0x70))

__device__ __forceinline__ uint32_t smem_u32(const void* p) {
    uint32_t a;
    asm("{ .reg .u64 t; cvta.to.shared.u64 t, %1; cvt.u32.u64 %0, t; }" : "=r"(a) : "l"(p));
    return a;
}
__device__ __forceinline__ void sts128(uint4 v, uint32_t addr) {
    asm volatile("st.shared.v4.b32 [%0], {%1, %2, %3, %4};"
                 :: "r"(addr), "r"(v.x), "r"(v.y), "r"(v.z), "r"(v.w) : "memory");
}
__device__ __forceinline__ void ldmatrix_x4(uint32_t* r, uint32_t addr) {
    asm volatile("ldmatrix.sync.aligned.m8n8.x4.shared.b16 {%0, %1, %2, %3}, [%4];"
                 : "=r"(r[0]), "=r"(r[1]), "=r"(r[2]), "=r"(r[3]) : "r"(addr));
}
__device__ __forceinline__ void mma16816(float* d, const uint32_t* a, const uint32_t* b) {
    asm volatile("mma.sync.aligned.m16n8k16.row.col.f32.f16.f16.f32 "
                 "{%0, %1, %2, %3}, {%4, %5, %6, %7}, {%8, %9}, {%0, %1, %2, %3};"
                 : "+f"(d[0]), "+f"(d[1]), "+f"(d[2]), "+f"(d[3])
                 : "r"(a[0]), "r"(a[1]), "r"(a[2]), "r"(a[3]), "r"(b[0]), "r"(b[1]));
}

__global__ __launch_bounds__(256)
void conv3x3_hmma3(const float* __restrict__ x,
                   const float* __restrict__ wgt,
                   const float* __restrict__ bias,
                   float* __restrict__ out) {
    extern __shared__ char smem[];
    const uint32_t sb   = smem_u32(smem);
    const int tid  = threadIdx.x;
    const int wid  = tid >> 5;
    const int lane = tid & 31;

    // ---- Build B (weights, fp16 hi/lo 3-col split) once per CTA ----
    for (int i = tid; i < NCHUNK * 64; i += 256) {
        int chunk = i >> 6, oc = i & 63;
        __align__(16) __half cols[64];
        #pragma unroll
        for (int q = 0; q < 64; q++) cols[q] = __ushort_as_half(0);
        #pragma unroll
        for (int cl = 0; cl < 2; cl++) {
            int c = chunk * 2 + cl;
            #pragma unroll
            for (int t = 0; t < 9; t++) {
                float w  = wgt[oc * (CIN * 9) + c * 9 + t];
                __half h = __float2half_rn(w);
                __half l = __float2half_rn(w - __half2float(h));
                cols[cl * 32 + t * 3 + 0] = h;
                cols[cl * 32 + t * 3 + 1] = h;
                cols[cl * 32 + t * 3 + 2] = l;
            }
        }
        const uint4* src = reinterpret_cast<const uint4*>(cols);
        #pragma unroll
        for (int q = 0; q < 8; q++) {
            uint32_t off = (uint32_t)oc * 128 + q * 16;
            sts128(src[q], sb + SMEM_B + chunk * 8192 + SW(off));
        }
    }

    // 8 warps: 4 (M) x 2 (N); warp tile 64 px x 32 oc; strip = full 256-px row.
    const int wm = wid & 3;
    const int wn = wid >> 2;

    float bv[4][2];
    #pragma unroll
    for (int nt = 0; nt < 4; nt++) {
        int oc0 = wn * 32 + nt * 8 + (lane & 3) * 2;
        bv[nt][0] = bias[oc0];
        bv[nt][1] = bias[oc0 + 1];
    }

    const int tsel = lane >> 3, rr = lane & 7;
    const int bg   = lane >> 3;
    const int px   = tid;     // this thread builds pixel px (0..255), both channels

    #pragma unroll 1
    for (int si = 0; si < 8; si++) {
        const int s = blockIdx.x * 8 + si;
        const int n = s >> 8;
        const int y = s & 255;

        __syncthreads();   // previous strip's MMAs done before overwriting A bufs

        // Prefetch chunk-0 taps (channels 0,1).
        float v[2][9];
        #pragma unroll
        for (int cl = 0; cl < 2; cl++) {
            const float* base = x + ((long)(n * CIN + cl) * HH) * WW;
            #pragma unroll
            for (int ky = 0; ky < 3; ky++) {
                int ry = y + ky - 1;
                bool rv = (unsigned)ry < HH;
                const float* r = base + (long)ry * WW + px - 1;
                #pragma unroll
                for (int kx = 0; kx < 3; kx++) {
                    int gxx = px + kx - 1;
                    v[cl][ky * 3 + kx] = (rv && (unsigned)gxx < WW) ? r[kx] : 0.0f;
                }
            }
        }

        float acc[4][4][4];
        #pragma unroll
        for (int mt = 0; mt < 4; mt++)
            #pragma unroll
            for (int nt = 0; nt < 4; nt++)
                #pragma unroll
                for (int q = 0; q < 4; q++) acc[mt][nt][q] = 0.0f;

        #pragma unroll 1
        for (int k = 0; k < NCHUNK; k++) {
            const uint32_t abase = sb + ((k & 1) ? SMEM_A1 : SMEM_A0);

            // Build A rows (both channel halves) from prefetched taps.
            #pragma unroll
            for (int cl = 0; cl < 2; cl++) {
                __align__(16) __half a[32];
                #pragma unroll
                for (int t = 0; t < 9; t++) {
                    float f  = v[cl][t];
                    __half h = __float2half_rn(f);
                    __half l = __float2half_rn(f - __half2float(h));
                    a[t * 3 + 0] = h;
                    a[t * 3 + 1] = l;
                    a[t * 3 + 2] = h;
                }
                #pragma unroll
                for (int q = 27; q < 32; q++) a[q] = __ushort_as_half(0);
                const uint4* src = reinterpret_cast<const uint4*>(a);
                uint32_t rowoff = (uint32_t)px * 128 + cl * 64;
                #pragma unroll
                for (int q = 0; q < 4; q++)
                    sts128(src[q], abase + SW(rowoff + q * 16));
            }

            // Prefetch next chunk's taps (LDGs fly through sync + MMA).
            if (k + 1 < NCHUNK) {
                #pragma unroll
                for (int cl = 0; cl < 2; cl++) {
                    const int c = (k + 1) * 2 + cl;
                    const float* base = x + ((long)(n * CIN + c) * HH) * WW;
                    #pragma unroll
                    for (int ky = 0; ky < 3; ky++) {
                        int ry = y + ky - 1;
                        bool rv = (unsigned)ry < HH;
                        const float* r = base + (long)ry * WW + px - 1;
                        #pragma unroll
                        for (int kx = 0; kx < 3; kx++) {
                            int gxx = px + kx - 1;
                            v[cl][ky * 3 + kx] = (rv && (unsigned)gxx < WW) ? r[kx] : 0.0f;
                        }
                    }
                }
            }

            __syncthreads();

            // MMA: 4 k16 steps, warp tile 64x32 over the 256-row A.
            const uint32_t bbase = sb + SMEM_B + k * 8192;
            #pragma unroll
            for (int st = 0; st < 4; st++) {
                uint32_t afr[4][4];
                #pragma unroll
                for (int mt = 0; mt < 4; mt++) {
                    int row = wm * 64 + mt * 16 + (tsel & 1) * 8 + rr;
                    uint32_t off = (uint32_t)row * 128 + st * 32 + (tsel >> 1) * 16;
                    ldmatrix_x4(afr[mt], abase + SW(off));
                }
                uint32_t bfr[4][2];
                #pragma unroll
                for (int p = 0; p < 2; p++) {
                    int row = wn * 32 + p * 16 + (bg >> 1) * 8 + rr;
                    uint32_t off = (uint32_t)row * 128 + st * 32 + (bg & 1) * 16;
                    uint32_t m[4];
                    ldmatrix_x4(m, bbase + SW(off));
                    bfr[2 * p][0]     = m[0];
                    bfr[2 * p][1]     = m[1];
                    bfr[2 * p + 1][0] = m[2];
                    bfr[2 * p + 1][1] = m[3];
                }
                #pragma unroll
                for (int mt = 0; mt < 4; mt++)
                    #pragma unroll
                    for (int nt = 0; nt < 4; nt++)
                        mma16816(acc[mt][nt], afr[mt], bfr[nt]);
            }
        }

        // ---- Epilogue: bias + store (full row y) ----
        float* outn = out + (long)n * OCN * HWX + (long)y * WW;
        #pragma unroll
        for (int mt = 0; mt < 4; mt++) {
            int px0 = wm * 64 + mt * 16 + (lane >> 2);
            #pragma unroll
            for (int nt = 0; nt < 4; nt++) {
                int oc0 = wn * 32 + nt * 8 + (lane & 3) * 2;
                float* p = outn + (long)oc0 * HWX + px0;
                p[0]       = acc[mt][nt][0] + bv[nt][0];
                p[HWX]     = acc[mt][nt][1] + bv[nt][1];
                p[8]       = acc[mt][nt][2] + bv[nt][0];
                p[HWX + 8] = acc[mt][nt][3] + bv[nt][1];
            }
        }
    }
}

extern "C" void kernel_launch(void* const* d_in, const int* in_sizes, int n_in,
                              void* d_out, int out_size) {
    const float* x    = (const float*)d_in[0];
    const float* wgt  = (const float*)d_in[1];
    const float* bias = (const float*)d_in[2];
    float* out        = (float*)d_out;

    cudaFuncSetAttribute(conv3x3_hmma3, cudaFuncAttributeMaxDynamicSharedMemorySize, SMEM_TOTAL);
    conv3x3_hmma3<<<1024, 256, SMEM_TOTAL>>>(x, wgt, bias, out);
}

// round 9
// speedup vs baseline: 1.2716x; 1.2716x over previous
#include <cuda_runtime.h>
#include <cuda_fp16.h>
#include <cstdint>

#define CIN 18
#define HH  256
#define WW  256
#define OCN 64
#define HWX 65536
#define NCHUNK 9

#define SMEM_A 0                     // 8 warps x 2 bufs x 8192 B = 131072
#define SMEM_B 131072                // 9 chunks x 8192 B = 73728
#define SMEM_TOTAL 204800

#define SW(o) ((o) ^ (((o) >> 3) & 0x70))

__device__ __forceinline__ uint32_t smem_u32(const void* p) {
    uint32_t a;
    asm("{ .reg .u64 t; cvta.to.shared.u64 t, %1; cvt.u32.u64 %0, t; }" : "=r"(a) : "l"(p));
    return a;
}
__device__ __forceinline__ void sts128(uint4 v, uint32_t addr) {
    asm volatile("st.shared.v4.b32 [%0], {%1, %2, %3, %4};"
                 :: "r"(addr), "r"(v.x), "r"(v.y), "r"(v.z), "r"(v.w) : "memory");
}
__device__ __forceinline__ void ldmatrix_x4(uint32_t* r, uint32_t addr) {
    asm volatile("ldmatrix.sync.aligned.m8n8.x4.shared.b16 {%0, %1, %2, %3}, [%4];"
                 : "=r"(r[0]), "=r"(r[1]), "=r"(r[2]), "=r"(r[3]) : "r"(addr));
}
__device__ __forceinline__ void mma16816(float* d, const uint32_t* a, const uint32_t* b) {
    asm volatile("mma.sync.aligned.m16n8k16.row.col.f32.f16.f16.f32 "
                 "{%0, %1, %2, %3}, {%4, %5, %6, %7}, {%8, %9}, {%0, %1, %2, %3};"
                 : "+f"(d[0]), "+f"(d[1]), "+f"(d[2]), "+f"(d[3])
                 : "r"(a[0]), "r"(a[1]), "r"(a[2]), "r"(a[3]), "r"(b[0]), "r"(b[1]));
}

__global__ __launch_bounds__(256)
void conv3x3_hmma4(const float* __restrict__ x,
                   const float* __restrict__ wgt,
                   const float* __restrict__ bias,
                   float* __restrict__ out) {
    extern __shared__ char smem[];
    const uint32_t sb   = smem_u32(smem);
    const int tid  = threadIdx.x;
    const int wid  = tid >> 5;
    const int lane = tid & 31;

    // ---- Build B (weights, fp16 hi/lo 3-col split) once per CTA ----
    for (int i = tid; i < NCHUNK * 64; i += 256) {
        int chunk = i >> 6, oc = i & 63;
        __align__(16) __half cols[64];
        #pragma unroll
        for (int q = 0; q < 64; q++) cols[q] = __ushort_as_half(0);
        #pragma unroll
        for (int cl = 0; cl < 2; cl++) {
            int c = chunk * 2 + cl;
            #pragma unroll
            for (int t = 0; t < 9; t++) {
                float w  = wgt[oc * (CIN * 9) + c * 9 + t];
                __half h = __float2half_rn(w);
                __half l = __float2half_rn(w - __half2float(h));
                cols[cl * 32 + t * 3 + 0] = h;
                cols[cl * 32 + t * 3 + 1] = h;
                cols[cl * 32 + t * 3 + 2] = l;
            }
        }
        const uint4* src = reinterpret_cast<const uint4*>(cols);
        #pragma unroll
        for (int q = 0; q < 8; q++) {
            uint32_t off = (uint32_t)oc * 128 + q * 16;
            sts128(src[q], sb + SMEM_B + chunk * 8192 + SW(off));
        }
    }
    __syncthreads();   // B ready; the ONLY CTA barrier

    // Warp geometry: strip = 2 image rows x 256 px. Warp owns 64 px of one row.
    const int wy = wid >> 2;                 // row within strip (0/1)
    const int Xw = (wid & 3) * 64;           // x-range base
    const int x0 = Xw + 2 * lane;            // this thread's even px
    const uint32_t abase0 = sb + SMEM_A + (uint32_t)wid * 16384;

    const bool lok = (x0 > 0);
    const bool rok = (x0 + 2 < WW);
    const int tsel = lane >> 3, rr = lane & 7;
    const int r0 = 2 * lane, r1 = 2 * lane + 1;   // warp-local A rows

    #pragma unroll 1
    for (int si = 0; si < 4; si++) {
        const int s = blockIdx.x * 4 + si;
        const int n = s >> 7;
        const int y = ((s & 127) << 1) + wy;
        const float* xs = x + (long)n * CIN * HWX;
        const bool t0 = (y > 0);
        const bool t2 = (y < HH - 1);

        float q[2][3][4];
        // Prefetch chunk 0 taps.
        #pragma unroll
        for (int cl = 0; cl < 2; cl++) {
            const float* base = xs + (long)cl * HWX;
            #pragma unroll
            for (int ky = 0; ky < 3; ky++) {
                bool rv = (ky == 0) ? t0 : (ky == 2) ? t2 : true;
                const float* r = base + (long)(y + ky - 1) * WW + x0;
                if (rv) {
                    q[cl][ky][0] = lok ? r[-1] : 0.0f;
                    float2 m = *reinterpret_cast<const float2*>(r);
                    q[cl][ky][1] = m.x; q[cl][ky][2] = m.y;
                    q[cl][ky][3] = rok ? r[2] : 0.0f;
                } else {
                    q[cl][ky][0] = q[cl][ky][1] = q[cl][ky][2] = q[cl][ky][3] = 0.0f;
                }
            }
        }

        float acc[4][8][4];
        #pragma unroll
        for (int mt = 0; mt < 4; mt++)
            #pragma unroll
            for (int nt = 0; nt < 8; nt++)
                #pragma unroll
                for (int qq = 0; qq < 4; qq++) acc[mt][nt][qq] = 0.0f;

        #pragma unroll 1
        for (int k = 0; k < NCHUNK; k++) {
            const uint32_t abuf = abase0 + (uint32_t)(k & 1) * 8192;

            // ---- Build A (2 px rows, 2 channels) into warp-private buffer ----
            #pragma unroll
            for (int cl = 0; cl < 2; cl++) {
                __half hh[3][4], hl[3][4];
                #pragma unroll
                for (int ky = 0; ky < 3; ky++)
                    #pragma unroll
                    for (int j = 0; j < 4; j++) {
                        float f  = q[cl][ky][j];
                        __half h = __float2half_rn(f);
                        hh[ky][j] = h;
                        hl[ky][j] = __float2half_rn(f - __half2float(h));
                    }
                __align__(16) __half a[32];
                #pragma unroll
                for (int qq = 27; qq < 32; qq++) a[qq] = __ushort_as_half(0);
                // px0 row
                #pragma unroll
                for (int ky = 0; ky < 3; ky++)
                    #pragma unroll
                    for (int kx = 0; kx < 3; kx++) {
                        int t = ky * 3 + kx;
                        a[3 * t + 0] = hh[ky][kx];
                        a[3 * t + 1] = hl[ky][kx];
                        a[3 * t + 2] = hh[ky][kx];
                    }
                {
                    const uint4* src = reinterpret_cast<const uint4*>(a);
                    uint32_t ro = (uint32_t)r0 * 128 + cl * 64;
                    #pragma unroll
                    for (int qi = 0; qi < 4; qi++)
                        sts128(src[qi], abuf + SW(ro + qi * 16));
                }
                // px1 row
                #pragma unroll
                for (int ky = 0; ky < 3; ky++)
                    #pragma unroll
                    for (int kx = 0; kx < 3; kx++) {
                        int t = ky * 3 + kx;
                        a[3 * t + 0] = hh[ky][kx + 1];
                        a[3 * t + 1] = hl[ky][kx + 1];
                        a[3 * t + 2] = hh[ky][kx + 1];
                    }
                {
                    const uint4* src = reinterpret_cast<const uint4*>(a);
                    uint32_t ro = (uint32_t)r1 * 128 + cl * 64;
                    #pragma unroll
                    for (int qi = 0; qi < 4; qi++)
                        sts128(src[qi], abuf + SW(ro + qi * 16));
                }
            }
            __syncwarp();

            // Prefetch next chunk's taps (LDGs fly under the MMAs).
            if (k + 1 < NCHUNK) {
                #pragma unroll
                for (int cl = 0; cl < 2; cl++) {
                    const float* base = xs + (long)((k + 1) * 2 + cl) * HWX;
                    #pragma unroll
                    for (int ky = 0; ky < 3; ky++) {
                        bool rv = (ky == 0) ? t0 : (ky == 2) ? t2 : true;
                        const float* r = base + (long)(y + ky - 1) * WW + x0;
                        if (rv) {
                            q[cl][ky][0] = lok ? r[-1] : 0.0f;
                            float2 m = *reinterpret_cast<const float2*>(r);
                            q[cl][ky][1] = m.x; q[cl][ky][2] = m.y;
                            q[cl][ky][3] = rok ? r[2] : 0.0f;
                        } else {
                            q[cl][ky][0] = q[cl][ky][1] = q[cl][ky][2] = q[cl][ky][3] = 0.0f;
                        }
                    }
                }
            }

            // ---- MMA: warp tile 64 px x 64 oc, 4 k16 steps ----
            const uint32_t bb = sb + SMEM_B + k * 8192;
            #pragma unroll
            for (int st = 0; st < 4; st++) {
                uint32_t bfr[8][2];
                #pragma unroll
                for (int p = 0; p < 4; p++) {
                    int row = p * 16 + (tsel >> 1) * 8 + rr;
                    uint32_t off = (uint32_t)row * 128 + st * 32 + (tsel & 1) * 16;
                    uint32_t m[4];
                    ldmatrix_x4(m, bb + SW(off));
                    bfr[2 * p][0]     = m[0];
                    bfr[2 * p][1]     = m[1];
                    bfr[2 * p + 1][0] = m[2];
                    bfr[2 * p + 1][1] = m[3];
                }
                #pragma unroll
                for (int mt = 0; mt < 4; mt++) {
                    uint32_t afr[4];
                    int row = mt * 16 + (tsel & 1) * 8 + rr;
                    uint32_t off = (uint32_t)row * 128 + st * 32 + (tsel >> 1) * 16;
                    ldmatrix_x4(afr, abuf + SW(off));
                    #pragma unroll
                    for (int nt = 0; nt < 8; nt++)
                        mma16816(acc[mt][nt], afr, bfr[nt]);
                }
            }
        }

        // ---- Epilogue: bias + store (warp's own 64 px of row y) ----
        float* ob = out + ((long)n * OCN) * HWX + (long)y * WW + Xw;
        #pragma unroll
        for (int nt = 0; nt < 8; nt++) {
            int oc0 = nt * 8 + (lane & 3) * 2;
            float b0 = bias[oc0], b1 = bias[oc0 + 1];
            float* p0 = ob + (long)oc0 * HWX;
            float* p1 = p0 + HWX;
            #pragma unroll
            for (int mt = 0; mt < 4; mt++) {
                int rl = mt * 16 + (lane >> 2);
                p0[rl]     = acc[mt][nt][0] + b0;
                p1[rl]     = acc[mt][nt][1] + b1;
                p0[rl + 8] = acc[mt][nt][2] + b0;
                p1[rl + 8] = acc[mt][nt][3] + b1;
            }
        }
    }
}

extern "C" void kernel_launch(void* const* d_in, const int* in_sizes, int n_in,
                              void* d_out, int out_size) {
    const float* x    = (const float*)d_in[0];
    const float* wgt  = (const float*)d_in[1];
    const float* bias = (const float*)d_in[2];
    float* out        = (float*)d_out;

    cudaFuncSetAttribute(conv3x3_hmma4, cudaFuncAttributeMaxDynamicSharedMemorySize, SMEM_TOTAL);
    conv3x3_hmma4<<<1024, 256, SMEM_TOTAL>>>(x, wgt, bias, out);
}

// round 10
// speedup vs baseline: 1.5212x; 1.1963x over previous
#include <cuda_runtime.h>
#include <cuda_fp16.h>
#include <cstdint>

#define CIN 18
#define HH  256
#define WW  256
#define OCN 64
#define HWX 65536
#define NCHUNK 6          // 3 channels per 64-col chunk, 2 cols per tap

#define SMEM_A 0                     // 8 warps x 2 bufs x 8192 B = 131072
#define SMEM_B 131072                // 6 chunks x 8192 B = 49152
#define SMEM_TOTAL 180224

#define SW(o) ((o) ^ (((o) >> 3) & 0x70))

__device__ __forceinline__ uint32_t smem_u32(const void* p) {
    uint32_t a;
    asm("{ .reg .u64 t; cvta.to.shared.u64 t, %1; cvt.u32.u64 %0, t; }" : "=r"(a) : "l"(p));
    return a;
}
__device__ __forceinline__ void sts128(uint4 v, uint32_t addr) {
    asm volatile("st.shared.v4.b32 [%0], {%1, %2, %3, %4};"
                 :: "r"(addr), "r"(v.x), "r"(v.y), "r"(v.z), "r"(v.w) : "memory");
}
__device__ __forceinline__ void ldmatrix_x4(uint32_t* r, uint32_t addr) {
    asm volatile("ldmatrix.sync.aligned.m8n8.x4.shared.b16 {%0, %1, %2, %3}, [%4];"
                 : "=r"(r[0]), "=r"(r[1]), "=r"(r[2]), "=r"(r[3]) : "r"(addr));
}
__device__ __forceinline__ void mma16816(float* d, const uint32_t* a, const uint32_t* b) {
    asm volatile("mma.sync.aligned.m16n8k16.row.col.f32.f16.f16.f32 "
                 "{%0, %1, %2, %3}, {%4, %5, %6, %7}, {%8, %9}, {%0, %1, %2, %3};"
                 : "+f"(d[0]), "+f"(d[1]), "+f"(d[2]), "+f"(d[3])
                 : "r"(a[0]), "r"(a[1]), "r"(a[2]), "r"(a[3]), "r"(b[0]), "r"(b[1]));
}

__global__ __launch_bounds__(256)
void conv3x3_hmma5(const float* __restrict__ x,
                   const float* __restrict__ wgt,
                   const float* __restrict__ bias,
                   float* __restrict__ out) {
    extern __shared__ char smem[];
    const uint32_t sb   = smem_u32(smem);
    const int tid  = threadIdx.x;
    const int wid  = tid >> 5;
    const int lane = tid & 31;

    // ---- Build B once per CTA: chunk = 3 channels x 9 taps x (wh, wh) cols ----
    for (int i = tid; i < NCHUNK * 64; i += 256) {
        int chunk = i >> 6, oc = i & 63;
        __align__(16) __half cols[64];
        #pragma unroll
        for (int q = 0; q < 64; q++) cols[q] = __ushort_as_half(0);
        #pragma unroll
        for (int cl = 0; cl < 3; cl++) {
            int c = chunk * 3 + cl;
            #pragma unroll
            for (int t = 0; t < 9; t++) {
                __half h = __float2half_rn(wgt[oc * (CIN * 9) + c * 9 + t]);
                cols[cl * 18 + 2 * t + 0] = h;
                cols[cl * 18 + 2 * t + 1] = h;
            }
        }
        const uint4* src = reinterpret_cast<const uint4*>(cols);
        #pragma unroll
        for (int q = 0; q < 8; q++) {
            uint32_t off = (uint32_t)oc * 128 + q * 16;
            sts128(src[q], sb + SMEM_B + chunk * 8192 + SW(off));
        }
    }
    __syncthreads();   // B ready; the ONLY CTA barrier

    // Warp geometry: strip = 2 image rows x 256 px. Warp owns 64 px of one row.
    const int wy = wid >> 2;
    const int Xw = (wid & 3) * 64;
    const int x0 = Xw + 2 * lane;
    const uint32_t abase0 = sb + SMEM_A + (uint32_t)wid * 16384;

    const bool lok = (x0 > 0);
    const bool rok = (x0 + 2 < WW);
    const int tsel = lane >> 3, rr = lane & 7;
    const int r0 = 2 * lane, r1 = 2 * lane + 1;

    #pragma unroll 1
    for (int si = 0; si < 4; si++) {
        const int s = blockIdx.x * 4 + si;
        const int n = s >> 7;
        const int y = ((s & 127) << 1) + wy;
        const float* xs = x + (long)n * CIN * HWX;
        const bool t0 = (y > 0);
        const bool t2 = (y < HH - 1);

        float q[3][3][4];
        // Prefetch chunk-0 taps (channels 0..2).
        #pragma unroll
        for (int cl = 0; cl < 3; cl++) {
            const float* base = xs + (long)cl * HWX;
            #pragma unroll
            for (int ky = 0; ky < 3; ky++) {
                bool rv = (ky == 0) ? t0 : (ky == 2) ? t2 : true;
                const float* r = base + (long)(y + ky - 1) * WW + x0;
                if (rv) {
                    q[cl][ky][0] = lok ? r[-1] : 0.0f;
                    float2 m = *reinterpret_cast<const float2*>(r);
                    q[cl][ky][1] = m.x; q[cl][ky][2] = m.y;
                    q[cl][ky][3] = rok ? r[2] : 0.0f;
                } else {
                    q[cl][ky][0] = q[cl][ky][1] = q[cl][ky][2] = q[cl][ky][3] = 0.0f;
                }
            }
        }

        float acc[4][8][4];
        #pragma unroll
        for (int mt = 0; mt < 4; mt++)
            #pragma unroll
            for (int nt = 0; nt < 8; nt++)
                #pragma unroll
                for (int qq = 0; qq < 4; qq++) acc[mt][nt][qq] = 0.0f;

        #pragma unroll 1
        for (int k = 0; k < NCHUNK; k++) {
            const uint32_t abuf = abase0 + (uint32_t)(k & 1) * 8192;

            // ---- Build A (2 px rows x 3 channels, (xh, xl) per tap) ----
            __half hh[3][3][4], hl[3][3][4];
            #pragma unroll
            for (int cl = 0; cl < 3; cl++)
                #pragma unroll
                for (int ky = 0; ky < 3; ky++)
                    #pragma unroll
                    for (int j = 0; j < 4; j++) {
                        float f  = q[cl][ky][j];
                        __half h = __float2half_rn(f);
                        hh[cl][ky][j] = h;
                        hl[cl][ky][j] = __float2half_rn(f - __half2float(h));
                    }
            #pragma unroll
            for (int pxo = 0; pxo < 2; pxo++) {
                __align__(16) __half a[64];
                #pragma unroll
                for (int qq = 54; qq < 64; qq++) a[qq] = __ushort_as_half(0);
                #pragma unroll
                for (int cl = 0; cl < 3; cl++)
                    #pragma unroll
                    for (int ky = 0; ky < 3; ky++)
                        #pragma unroll
                        for (int kx = 0; kx < 3; kx++) {
                            int t = ky * 3 + kx;
                            a[cl * 18 + 2 * t + 0] = hh[cl][ky][kx + pxo];
                            a[cl * 18 + 2 * t + 1] = hl[cl][ky][kx + pxo];
                        }
                const uint4* src = reinterpret_cast<const uint4*>(a);
                uint32_t ro = (uint32_t)(pxo ? r1 : r0) * 128;
                #pragma unroll
                for (int qi = 0; qi < 8; qi++)
                    sts128(src[qi], abuf + SW(ro + qi * 16));
            }
            __syncwarp();

            // Prefetch next chunk's taps (LDGs fly under the MMAs).
            if (k + 1 < NCHUNK) {
                #pragma unroll
                for (int cl = 0; cl < 3; cl++) {
                    const float* base = xs + (long)((k + 1) * 3 + cl) * HWX;
                    #pragma unroll
                    for (int ky = 0; ky < 3; ky++) {
                        bool rv = (ky == 0) ? t0 : (ky == 2) ? t2 : true;
                        const float* r = base + (long)(y + ky - 1) * WW + x0;
                        if (rv) {
                            q[cl][ky][0] = lok ? r[-1] : 0.0f;
                            float2 m = *reinterpret_cast<const float2*>(r);
                            q[cl][ky][1] = m.x; q[cl][ky][2] = m.y;
                            q[cl][ky][3] = rok ? r[2] : 0.0f;
                        } else {
                            q[cl][ky][0] = q[cl][ky][1] = q[cl][ky][2] = q[cl][ky][3] = 0.0f;
                        }
                    }
                }
            }

            // ---- MMA: warp tile 64 px x 64 oc, 4 k16 steps ----
            const uint32_t bb = sb + SMEM_B + k * 8192;
            #pragma unroll
            for (int st = 0; st < 4; st++) {
                uint32_t bfr[8][2];
                #pragma unroll
                for (int p = 0; p < 4; p++) {
                    int row = p * 16 + (tsel >> 1) * 8 + rr;
                    uint32_t off = (uint32_t)row * 128 + st * 32 + (tsel & 1) * 16;
                    uint32_t m[4];
                    ldmatrix_x4(m, bb + SW(off));
                    bfr[2 * p][0]     = m[0];
                    bfr[2 * p][1]     = m[1];
                    bfr[2 * p + 1][0] = m[2];
                    bfr[2 * p + 1][1] = m[3];
                }
                #pragma unroll
                for (int mt = 0; mt < 4; mt++) {
                    uint32_t afr[4];
                    int row = mt * 16 + (tsel & 1) * 8 + rr;
                    uint32_t off = (uint32_t)row * 128 + st * 32 + (tsel >> 1) * 16;
                    ldmatrix_x4(afr, abuf + SW(off));
                    #pragma unroll
                    for (int nt = 0; nt < 8; nt++)
                        mma16816(acc[mt][nt], afr, bfr[nt]);
                }
            }
        }

        // ---- Epilogue: bias + store (warp's own 64 px of row y) ----
        float* ob = out + ((long)n * OCN) * HWX + (long)y * WW + Xw;
        #pragma unroll
        for (int nt = 0; nt < 8; nt++) {
            int oc0 = nt * 8 + (lane & 3) * 2;
            float b0 = bias[oc0], b1 = bias[oc0 + 1];
            float* p0 = ob + (long)oc0 * HWX;
            float* p1 = p0 + HWX;
            #pragma unroll
            for (int mt = 0; mt < 4; mt++) {
                int rl = mt * 16 + (lane >> 2);
                p0[rl]     = acc[mt][nt][0] + b0;
                p1[rl]     = acc[mt][nt][1] + b1;
                p0[rl + 8] = acc[mt][nt][2] + b0;
                p1[rl + 8] = acc[mt][nt][3] + b1;
            }
        }
    }
}

extern "C" void kernel_launch(void* const* d_in, const int* in_sizes, int n_in,
                              void* d_out, int out_size) {
    const float* x    = (const float*)d_in[0];
    const float* wgt  = (const float*)d_in[1];
    const float* bias = (const float*)d_in[2];
    float* out        = (float*)d_out;

    cudaFuncSetAttribute(conv3x3_hmma5, cudaFuncAttributeMaxDynamicSharedMemorySize, SMEM_TOTAL);
    conv3x3_hmma5<<<1024, 256, SMEM_TOTAL>>>(x, wgt, bias, out);
}